// round 2
// baseline (speedup 1.0000x reference)
#include <cuda_runtime.h>
#include <cuda_bf16.h>

// One wave: 148 SMs x 8 CTAs of 256 threads.
#define NBLK 1184

__device__ float        g_partials[NBLK];
__device__ unsigned int g_done = 0;   // reset by last block each run -> deterministic

// term(x, pos) = softplus(x) - x*[pos], numerically stable.
__device__ __forceinline__ float bce_term(float v, bool pos) {
    float sp = fmaxf(v, 0.0f) + __logf(1.0f + __expf(-fabsf(v)));
    return pos ? sp - v : sp;
}

__global__ __launch_bounds__(256) void bce_fused(
    const float* __restrict__ x,
    const long long* __restrict__ tg,
    float* __restrict__ out,
    int B, int N, float inv_count)
{
    const int n4 = N >> 2;
    float s = 0.0f;

    for (int row = blockIdx.x; row < B; row += gridDim.x) {
        const float4* __restrict__ xr =
            reinterpret_cast<const float4*>(x + (size_t)row * N);
        const long long t = tg[row];

        if (n4 == 2048) {
            // Fast path for N=8192: fixed 8 iterations -> front-batched LDG.128 (MLP=8)
            #pragma unroll
            for (int i = 0; i < 8; i++) {
                const int idx = threadIdx.x + (i << 8);
                float4 v = xr[idx];
                const long long c = (long long)idx * 4;
                s += bce_term(v.x, c + 0 < t);
                s += bce_term(v.y, c + 1 < t);
                s += bce_term(v.z, c + 2 < t);
                s += bce_term(v.w, c + 3 < t);
            }
        } else {
            for (int idx = threadIdx.x; idx < n4; idx += blockDim.x) {
                float4 v = xr[idx];
                const long long c = (long long)idx * 4;
                s += bce_term(v.x, c + 0 < t);
                s += bce_term(v.y, c + 1 < t);
                s += bce_term(v.z, c + 2 < t);
                s += bce_term(v.w, c + 3 < t);
            }
        }
    }

    // ---- block reduction (float) ----
    #pragma unroll
    for (int o = 16; o > 0; o >>= 1)
        s += __shfl_xor_sync(0xFFFFFFFFu, s, o);

    __shared__ float warp_sums[8];
    const int lane = threadIdx.x & 31;
    const int wid  = threadIdx.x >> 5;
    if (lane == 0) warp_sums[wid] = s;
    __syncthreads();

    float block_sum = 0.0f;
    if (threadIdx.x < 32) {
        float v = (lane < 8) ? warp_sums[lane] : 0.0f;
        #pragma unroll
        for (int o = 4; o > 0; o >>= 1)
            v += __shfl_xor_sync(0xFFFFFFFFu, v, o);
        block_sum = v;
    }

    // ---- last-block-done tail reduction ----
    __shared__ bool is_last;
    if (threadIdx.x == 0) {
        g_partials[blockIdx.x] = block_sum;
        __threadfence();
        unsigned int ticket = atomicAdd(&g_done, 1u);
        is_last = (ticket == gridDim.x - 1);
    }
    __syncthreads();

    if (is_last) {
        double d = 0.0;
        for (int i = threadIdx.x; i < (int)gridDim.x; i += blockDim.x)
            d += (double)g_partials[i];

        #pragma unroll
        for (int o = 16; o > 0; o >>= 1)
            d += __shfl_xor_sync(0xFFFFFFFFu, d, o);

        __shared__ double dwarp[8];
        if (lane == 0) dwarp[wid] = d;
        __syncthreads();

        if (threadIdx.x < 32) {
            double v = (lane < 8) ? dwarp[lane] : 0.0;
            #pragma unroll
            for (int o = 4; o > 0; o >>= 1)
                v += __shfl_xor_sync(0xFFFFFFFFu, v, o);
            if (lane == 0) {
                out[0] = (float)(v * (double)inv_count);
                g_done = 0;  // reset for next (graph replay) run
            }
        }
    }
}

extern "C" void kernel_launch(void* const* d_in, const int* in_sizes, int n_in,
                              void* d_out, int out_size)
{
    const float*     x  = (const float*)d_in[0];
    const long long* tg = (const long long*)d_in[1];
    float* out = (float*)d_out;

    const int B = in_sizes[1];        // 8192 rows (one target per row)
    const int N = in_sizes[0] / B;    // 8192 cols

    const float inv_count = (float)(1.0 / ((double)B * (double)N));
    bce_fused<<<NBLK, 256>>>(x, tg, out, B, N, inv_count);
}